// round 15
// baseline (speedup 1.0000x reference)
#include <cuda_runtime.h>
#include <cuda_fp16.h>
#include <cstdint>

typedef uint32_t u32;

// ---------------------------------------------------------------------------
// Triaffine, tensor-core fp16 mma (fp32 accum), 3 launches total:
//  prep_all: fp32->fp16 casts of l1/l2/W1/W2 + W3 transpose  (one kernel)
//  K1: X{1,2} = l1(fp16) @ W{1,2}(fp16) + bias  -> g_X fp16   (BK=64, 4 stages)
//  K23 (fused, per (m, 128-j tile)):
//    s1: A_r = l2 @ X2 + bias, *h2  -> smem P (single fp16)
//    s2: T   = P @ W3T (1-term), *h1 -> smem fp32 (overwrites P)
//    s3: A_l = l2 @ X1 + bias;  out[j] = sum_c A_l[j,c] * T[j,c]
// ---------------------------------------------------------------------------

#define WSZ 16908544ull              // 257*65792
#define XSZ (2048ull*65792)

__device__ __half g_L1[2048ull*256], g_L2[2048ull*256];
__device__ __half g_W[2ull*WSZ];                   // W1 | W2 (fp16)
__device__ __half g_X[2ull*XSZ];                   // X1 | X2 (fp16)
__device__ __half g_W3T[256*256];                  // W3T[d][c] (fp16)

// ---- K1 smem (256 threads, 2 CTA/SM): [A 16384 | B 16384] x 3, BK=64 ----
#define K1BUF   32768
#define SMEM12  98304

// ---- K23 smem (512 threads, 1 CTA/SM) ----
#define FBUF    24576                // [A 8192 | B 16384] x 3
#define FSM_P   73728                // P fp16 64KB; T fp32 (133120B) overlaps
#define FSM_H   206848               // h1 1KB | h2 1KB
#define FSM_RED 208896               // 4 x 128 floats
#define FSMEM   210944

// ---------------- PTX helpers ----------------
__device__ __forceinline__ u32 smem_u32(const void* p) {
    u32 a;
    asm("{ .reg .u64 t; cvta.to.shared.u64 t, %1; cvt.u32.u64 %0, t; }" : "=r"(a) : "l"(p));
    return a;
}
__device__ __forceinline__ void cpa16(u32 s, const void* g) {
    asm volatile("cp.async.cg.shared.global [%0], [%1], 16;" :: "r"(s), "l"(g));
}
#define CPA_COMMIT() asm volatile("cp.async.commit_group;" ::: "memory")
#define CPA_WAIT(n)  asm volatile("cp.async.wait_group %0;" :: "n"(n) : "memory")

__device__ __forceinline__ void ldm_x4(u32 addr, u32 r[4]) {
    asm volatile("ldmatrix.sync.aligned.m8n8.x4.shared.b16 {%0,%1,%2,%3}, [%4];"
        : "=r"(r[0]), "=r"(r[1]), "=r"(r[2]), "=r"(r[3]) : "r"(addr));
}
__device__ __forceinline__ void ldm_x4_t(u32 addr, u32 r[4]) {
    asm volatile("ldmatrix.sync.aligned.m8n8.x4.trans.shared.b16 {%0,%1,%2,%3}, [%4];"
        : "=r"(r[0]), "=r"(r[1]), "=r"(r[2]), "=r"(r[3]) : "r"(addr));
}
__device__ __forceinline__ void mma_f16(float c[4], const u32 a[4], u32 b0, u32 b1) {
    asm volatile("mma.sync.aligned.m16n8k16.row.col.f32.f16.f16.f32 "
        "{%0,%1,%2,%3}, {%4,%5,%6,%7}, {%8,%9}, {%0,%1,%2,%3};"
        : "+f"(c[0]), "+f"(c[1]), "+f"(c[2]), "+f"(c[3])
        : "r"(a[0]), "r"(a[1]), "r"(a[2]), "r"(a[3]), "r"(b0), "r"(b1));
}

// XOR swizzles (c = 16B chunk index within row)
__device__ __forceinline__ u32 sw_a(u32 base, int row, int c) {       // 64B rows
    return base + row * 64 + ((c ^ ((row >> 1) & 3)) << 4);
}
__device__ __forceinline__ u32 sw_a128(u32 base, int row, int c) {    // 128B rows
    return base + row * 128 + ((c ^ (row & 7)) << 4);
}
__device__ __forceinline__ u32 sw_b(u32 base, int row, int c) {       // 256B rows
    return base + row * 256 + ((c ^ (row & 7)) << 4);
}
__device__ __forceinline__ u32 sw_b512(u32 base, int row, int c) {    // 512B rows
    return base + row * 512 + ((c ^ (row & 7)) << 4);
}

#define ZERO_ACC(acc)                                                         \
    _Pragma("unroll") for (int mi = 0; mi < 2; ++mi)                          \
    _Pragma("unroll") for (int ni = 0; ni < 8; ++ni)                          \
    _Pragma("unroll") for (int q = 0; q < 4; ++q) acc[mi][ni][q] = 0.0f;

// ---------------------------------------------------------------------------
// K1 building blocks (256 threads, BK=64, CTA 128x128)
// ---------------------------------------------------------------------------
__device__ __forceinline__ void stage64(u32 base, int tid,
    const __half* __restrict__ a, size_t apitch,
    const __half* __restrict__ b, size_t bpitch, int k0)
{
    const int arow = tid >> 1, ac = (tid & 1) * 4;       // A: 128 rows x 8 chunks
    const __half* ga = a + (size_t)arow * apitch + k0 + ac * 8;
#pragma unroll
    for (int i = 0; i < 4; ++i)
        cpa16(sw_a128(base, arow, ac + i), ga + i * 8);
    const int brow = tid >> 2, bc = (tid & 3) * 4;       // B: 64 rows x 16 chunks
    const __half* gb = b + (size_t)(k0 + brow) * bpitch + bc * 8;
#pragma unroll
    for (int i = 0; i < 4; ++i)
        cpa16(sw_b(base + 16384, brow, bc + i), gb + i * 8);
}
__device__ __forceinline__ void compute64k(float acc[2][8][4],
        u32 base, int warpM, int warpN, int lane)
{
    const int lr = lane & 15, lh = lane >> 4;
#pragma unroll
    for (int kk = 0; kk < 4; ++kk) {
        u32 af[2][4];
#pragma unroll
        for (int mi = 0; mi < 2; ++mi)
            ldm_x4(sw_a128(base, warpM * 32 + mi * 16 + lr, kk * 2 + lh), af[mi]);
#pragma unroll
        for (int np = 0; np < 4; ++np) {
            u32 bf[4];
            ldm_x4_t(sw_b(base + 16384, kk * 16 + lr, warpN * 8 + np * 2 + lh), bf);
#pragma unroll
            for (int mi = 0; mi < 2; ++mi) {
                mma_f16(acc[mi][np*2],   af[mi], bf[0], bf[1]);
                mma_f16(acc[mi][np*2+1], af[mi], bf[2], bf[3]);
            }
        }
    }
}

// ---------------------------------------------------------------------------
// K23 building blocks (512 threads, B rows 512B, CTA 128x256) — unchanged R14
// ---------------------------------------------------------------------------
__device__ __forceinline__ void stage_f(u32 base, int tid,
    const __half* __restrict__ a, const __half* __restrict__ b, int k0)
{
    const int arow = tid >> 2, ac = tid & 3;
    cpa16(sw_a(base, arow, ac), a + (size_t)arow * 256 + k0 + ac * 8);
    const int brow = tid >> 4, bc = (tid & 15) * 2;
    const __half* g = b + (size_t)(k0 + brow) * 256 + bc * 8;
    cpa16(sw_b512(base + 8192, brow, bc), g);
    cpa16(sw_b512(base + 8192, brow, bc + 1), g + 8);
}
__device__ __forceinline__ void stage_fB(u32 base, int tid,
    const __half* __restrict__ b, int k0)
{
    const int brow = tid >> 4, bc = (tid & 15) * 2;
    const __half* g = b + (size_t)(k0 + brow) * 256 + bc * 8;
    cpa16(sw_b512(base, brow, bc), g);
    cpa16(sw_b512(base, brow, bc + 1), g + 8);
}
__device__ __forceinline__ void compute_f(float acc[2][8][4],
        u32 base, int warpM, int warpN, int lane)
{
    const int lr = lane & 15, lh = lane >> 4;
#pragma unroll
    for (int kk = 0; kk < 2; ++kk) {
        u32 af[2][4];
#pragma unroll
        for (int mi = 0; mi < 2; ++mi)
            ldm_x4(sw_a(base, warpM * 32 + mi * 16 + lr, kk * 2 + lh), af[mi]);
#pragma unroll
        for (int np = 0; np < 4; ++np) {
            u32 bf[4];
            ldm_x4_t(sw_b512(base + 8192, kk * 16 + lr, warpN * 8 + np * 2 + lh), bf);
#pragma unroll
            for (int mi = 0; mi < 2; ++mi) {
                mma_f16(acc[mi][np*2],   af[mi], bf[0], bf[1]);
                mma_f16(acc[mi][np*2+1], af[mi], bf[2], bf[3]);
            }
        }
    }
}
__device__ __forceinline__ void compute_fp1(float acc[2][8][4],
        u32 pHi, u32 bBase, int sChunk, int warpM, int warpN, int lane)
{
    const int lr = lane & 15, lh = lane >> 4;
#pragma unroll
    for (int kk = 0; kk < 2; ++kk) {
        u32 af[2][4];
#pragma unroll
        for (int mi = 0; mi < 2; ++mi) {
            int row = warpM * 32 + mi * 16 + lr;
            int c = sChunk + kk * 2 + lh;
            u32 off = row * 512 + (((c ^ (row & 7))) << 4);
            ldm_x4(pHi + off, af[mi]);
        }
#pragma unroll
        for (int np = 0; np < 4; ++np) {
            u32 bf[4];
            ldm_x4_t(sw_b512(bBase, kk * 16 + lr, warpN * 8 + np * 2 + lh), bf);
#pragma unroll
            for (int mi = 0; mi < 2; ++mi) {
                mma_f16(acc[mi][np*2],   af[mi], bf[0], bf[1]);
                mma_f16(acc[mi][np*2+1], af[mi], bf[2], bf[3]);
            }
        }
    }
}

// 3-buffer pipeline, prefetch depth 2, one barrier per BK=32 stage (K23)
#define FLOOP(STG, CMP)                                                       \
    STG(0, 0); CPA_COMMIT();                                                  \
    STG(1, 1); CPA_COMMIT();                                                  \
    for (int s = 0; s < 8; ++s) {                                             \
        if (s == 7) { CPA_WAIT(0); } else { CPA_WAIT(1); }                    \
        __syncthreads();                                                      \
        if (s < 6) { STG((s + 2) % 3, s + 2); CPA_COMMIT(); }                 \
        CMP;                                                                  \
    }

// ---------------------------------------------------------------------------
// prep_all: one kernel. blocks [0,256) L1, [256,512) L2, [512,8769) W1,
// [8769,17026) W2, [17026,17090) W3 transpose.
// ---------------------------------------------------------------------------
__global__ void k_prep_all(const float* __restrict__ layer1,
                           const float* __restrict__ layer2,
                           const float* __restrict__ W1,
                           const float* __restrict__ W2,
                           const float* __restrict__ W3)
{
    const int bid = blockIdx.x, tid = threadIdx.x;
    if (bid < 17026) {
        const float* src;
        __half* d;
        size_t base, cnt;
        if (bid < 256)       { src = layer1; d = g_L1;      base = (size_t)bid * 2048;           cnt = 524288ull; }
        else if (bid < 512)  { src = layer2; d = g_L2;      base = (size_t)(bid - 512 + 256) * 2048; cnt = 524288ull; }
        else if (bid < 8769) { src = W1;     d = g_W;       base = (size_t)(bid - 512) * 2048;   cnt = WSZ; }
        else                 { src = W2;     d = g_W + WSZ; base = (size_t)(bid - 8769) * 2048;  cnt = WSZ; }
        size_t i = base + (size_t)tid * 8;
        if (i >= cnt) return;
        float4 v0 = *reinterpret_cast<const float4*>(src + i);
        float4 v1 = *reinterpret_cast<const float4*>(src + i + 4);
        float x[8] = {v0.x, v0.y, v0.z, v0.w, v1.x, v1.y, v1.z, v1.w};
        u32 o[4];
#pragma unroll
        for (int j = 0; j < 4; ++j) {
            __half2 h = __floats2half2_rn(x[2*j], x[2*j+1]);
            o[j] = *reinterpret_cast<u32*>(&h);
        }
        *reinterpret_cast<uint4*>(d + i) = make_uint4(o[0], o[1], o[2], o[3]);
    } else {
        __shared__ float t[32][33];
        int tb = bid - 17026;
        int bx = (tb & 7) * 32, by = (tb >> 3) * 32;
        int r0 = tid >> 5, cc = tid & 31;
#pragma unroll
        for (int rr = r0; rr < 32; rr += 8)
            t[rr][cc] = W3[(size_t)(by + rr) * 256 + bx + cc];
        __syncthreads();
#pragma unroll
        for (int rr = r0; rr < 32; rr += 8)
            g_W3T[(size_t)(bx + rr) * 256 + by + cc] = __float2half_rn(t[cc][rr]);
    }
}

// ---------------------------------------------------------------------------
// K1: grid (16 mt, 514 nt, 2 w). D[128 m][128 bc], K=256 over a (4 x BK=64).
// ---------------------------------------------------------------------------
__global__ void __launch_bounds__(256, 2)
k1_gemm()
{
    extern __shared__ char smem[];
    const int tid = threadIdx.x, lane = tid & 31, wid = tid >> 5;
    const int warpM = wid & 3, warpN = wid >> 2;
    const int mBase = blockIdx.x * 128;
    const size_t n0 = (size_t)blockIdx.y * 128;
    const int w = blockIdx.z;
    const __half* WP = g_W + (size_t)w * WSZ + n0;
    __half* XP       = g_X + (size_t)w * XSZ;
    const __half* AP = g_L1 + (size_t)mBase * 256;
    const u32 sb = smem_u32(smem);

    float acc[2][8][4];
    ZERO_ACC(acc)

    stage64(sb, tid, AP, 256, WP, 65792, 0); CPA_COMMIT();
    stage64(sb + K1BUF, tid, AP, 256, WP, 65792, 64); CPA_COMMIT();
    for (int s = 0; s < 4; ++s) {
        if (s == 3) { CPA_WAIT(0); } else { CPA_WAIT(1); }
        __syncthreads();
        if (s < 2) {
            stage64(sb + ((s + 2) % 3) * K1BUF, tid, AP, 256, WP, 65792, (s + 2) * 64);
            CPA_COMMIT();
        }
        compute64k(acc, sb + (s % 3) * K1BUF, warpM, warpN, lane);
    }

    const int gq = lane >> 2, t = lane & 3;
#pragma unroll
    for (int mi = 0; mi < 2; ++mi) {
        int row = mBase + warpM * 32 + mi * 16 + gq;
#pragma unroll
        for (int ni = 0; ni < 8; ++ni) {
            int colL = warpN * 64 + ni * 8 + t * 2;
            __half2 b2 = *reinterpret_cast<const __half2*>(WP + 256ull * 65792 + colL);
            float b0 = __half2float(__low2half(b2));
            float b1 = __half2float(__high2half(b2));
            size_t col = n0 + colL;
            __half2 o0 = __floats2half2_rn(acc[mi][ni][0] + b0, acc[mi][ni][1] + b1);
            __half2 o1 = __floats2half2_rn(acc[mi][ni][2] + b0, acc[mi][ni][3] + b1);
            *reinterpret_cast<__half2*>(XP + (size_t)row * 65792 + col) = o0;
            *reinterpret_cast<__half2*>(XP + (size_t)(row + 8) * 65792 + col) = o1;
        }
    }
}

// ---------------------------------------------------------------------------
// K23 fused: grid (2 jt, 2048 m), 512 threads, CTA tile 128 j x 256 (c|d).
// ---------------------------------------------------------------------------
__global__ void __launch_bounds__(512, 1)
k23_fused(const float* __restrict__ h1, const float* __restrict__ h2,
          float* __restrict__ out)
{
    extern __shared__ char smem[];
    const int tid = threadIdx.x, lane = tid & 31, wid = tid >> 5;
    const int warpM = wid & 3, warpN = wid >> 2;     // 4 x 4 warps
    const int jt = blockIdx.x, m = blockIdx.y;
    const u32 sb = smem_u32(smem);
    const u32 pHi = sb + FSM_P;
    float* Tp  = reinterpret_cast<float*>(smem + FSM_P);     // pitch 260 floats
    float* h1s = reinterpret_cast<float*>(smem + FSM_H);
    float* h2s = reinterpret_cast<float*>(smem + FSM_H + 1024);
    float* red = reinterpret_cast<float*>(smem + FSM_RED);

    const __half* AP  = g_L2 + ((size_t)(m >> 8) * 256 + (size_t)jt * 128) * 256;
    const __half* X1P = g_X + (size_t)m * 65792;
    const __half* X2P = g_X + XSZ + (size_t)m * 65792;

    if (tid < 256) {
        h1s[tid] = h1[(size_t)m * 256 + tid];
        h2s[tid] = h2[(size_t)m * 256 + tid];
    }

    const int gq = lane >> 2, t = lane & 3;
    float acc[2][8][4];

    // ---------------- stage 1: A_r = l2 @ X2 + bias, *h2 -> P fp16 ----------
    ZERO_ACC(acc)
#define S1(buf, s) stage_f(sb + (buf) * FBUF, tid, AP, X2P, (s) * 32)
    FLOOP(S1, compute_f(acc, sb + (s % 3) * FBUF, warpM, warpN, lane))
#undef S1

#pragma unroll
    for (int mi = 0; mi < 2; ++mi) {
        int j0 = warpM * 32 + mi * 16 + gq;
#pragma unroll
        for (int ni = 0; ni < 8; ++ni) {
            int c = warpN * 64 + ni * 8 + t * 2;
            __half2 b2 = *reinterpret_cast<const __half2*>(X2P + 65536 + c);
            float b0 = __half2float(__low2half(b2));
            float b1 = __half2float(__high2half(b2));
            float v00 = (acc[mi][ni][0] + b0) * h2s[c];
            float v01 = (acc[mi][ni][1] + b1) * h2s[c + 1];
            float v10 = (acc[mi][ni][2] + b0) * h2s[c];
            float v11 = (acc[mi][ni][3] + b1) * h2s[c + 1];
            u32 chunk = (u32)(warpN * 8 + ni);
            u32 o0 = j0 * 512 + ((chunk ^ (j0 & 7)) << 4) + t * 4;
            int j1 = j0 + 8;
            u32 o1 = j1 * 512 + ((chunk ^ (j1 & 7)) << 4) + t * 4;
            *reinterpret_cast<__half2*>(smem + FSM_P + o0) =
                __floats2half2_rn(v00, v01);
            *reinterpret_cast<__half2*>(smem + FSM_P + o1) =
                __floats2half2_rn(v10, v11);
        }
    }
    __syncthreads();   // P complete before stage-2 staging/compute

    // ---------------- stage 2: T = P @ W3T (1-term), *h1 -> T ---------------
    ZERO_ACC(acc)
#define S2(buf, s) stage_fB(sb + (buf) * FBUF, tid, g_W3T, (s) * 32)
    FLOOP(S2, compute_fp1(acc, pHi, sb + (s % 3) * FBUF, s * 4, warpM, warpN, lane))
#undef S2

    __syncthreads();   // all P reads done; safe to overwrite with T
#pragma unroll
    for (int mi = 0; mi < 2; ++mi) {
        int j0 = warpM * 32 + mi * 16 + gq;
#pragma unroll
        for (int ni = 0; ni < 8; ++ni) {
            int c = warpN * 64 + ni * 8 + t * 2;
            float s0 = h1s[c], s1 = h1s[c + 1];
            *reinterpret_cast<float2*>(Tp + (size_t)j0 * 260 + c) =
                make_float2(acc[mi][ni][0] * s0, acc[mi][ni][1] * s1);
            *reinterpret_cast<float2*>(Tp + (size_t)(j0 + 8) * 260 + c) =
                make_float2(acc[mi][ni][2] * s0, acc[mi][ni][3] * s1);
        }
    }
    __syncthreads();   // T visible before stage-3 epilogue; bufs free

    // ---------------- stage 3: A_l = l2 @ X1 + bias; dot with T -------------
    ZERO_ACC(acc)
#define S3(buf, s) stage_f(sb + (buf) * FBUF, tid, AP, X1P, (s) * 32)
    FLOOP(S3, compute_f(acc, sb + (s % 3) * FBUF, warpM, warpN, lane))
#undef S3

    float rs[2][2] = {{0.0f, 0.0f}, {0.0f, 0.0f}};
#pragma unroll
    for (int mi = 0; mi < 2; ++mi) {
        int j0 = warpM * 32 + mi * 16 + gq;
#pragma unroll
        for (int ni = 0; ni < 8; ++ni) {
            int c = warpN * 64 + ni * 8 + t * 2;
            __half2 b2 = *reinterpret_cast<const __half2*>(X1P + 65536 + c);
            float b0 = __half2float(__low2half(b2));
            float b1 = __half2float(__high2half(b2));
            float2 t0 = *reinterpret_cast<const float2*>(Tp + (size_t)j0 * 260 + c);
            float2 t1 = *reinterpret_cast<const float2*>(Tp + (size_t)(j0 + 8) * 260 + c);
            rs[mi][0] += (acc[mi][ni][0] + b0) * t0.x + (acc[mi][ni][1] + b1) * t0.y;
            rs[mi][1] += (acc[mi][ni][2] + b0) * t1.x + (acc[mi][ni][3] + b1) * t1.y;
        }
    }

    // reduce over the 4 lanes (t) sharing each row, then across warpN
#pragma unroll
    for (int mi = 0; mi < 2; ++mi)
#pragma unroll
        for (int h = 0; h < 2; ++h) {
            rs[mi][h] += __shfl_xor_sync(0xffffffffu, rs[mi][h], 1);
            rs[mi][h] += __shfl_xor_sync(0xffffffffu, rs[mi][h], 2);
        }
    if (t == 0) {
#pragma unroll
        for (int mi = 0; mi < 2; ++mi) {
            red[warpN * 128 + warpM * 32 + mi * 16 + gq]     = rs[mi][0];
            red[warpN * 128 + warpM * 32 + mi * 16 + 8 + gq] = rs[mi][1];
        }
    }
    __syncthreads();
    if (tid < 128)
        out[(size_t)m * 256 + jt * 128 + tid] =
            red[tid] + red[128 + tid] + red[256 + tid] + red[384 + tid];
}

// ---------------------------------------------------------------------------
extern "C" void kernel_launch(void* const* d_in, const int* in_sizes, int n_in,
                              void* d_out, int out_size)
{
    const float* layer1 = (const float*)d_in[0];
    const float* layer2 = (const float*)d_in[1];
    const float* h1     = (const float*)d_in[2];
    const float* h2     = (const float*)d_in[3];
    const float* W1     = (const float*)d_in[4];
    const float* W2     = (const float*)d_in[5];
    const float* W3     = (const float*)d_in[6];
    float* out = (float*)d_out;

    cudaFuncSetAttribute(k1_gemm,   cudaFuncAttributeMaxDynamicSharedMemorySize, SMEM12);
    cudaFuncSetAttribute(k23_fused, cudaFuncAttributeMaxDynamicSharedMemorySize, FSMEM);

    k_prep_all<<<17090, 256>>>(layer1, layer2, W1, W2, W3);
    k1_gemm<<<dim3(16, 514, 2), 256, SMEM12>>>();
    k23_fused<<<dim3(2, 2048), 512, FSMEM>>>(h1, h2, out);
}

// round 16
// speedup vs baseline: 1.0443x; 1.0443x over previous
#include <cuda_runtime.h>
#include <cuda_fp16.h>
#include <cstdint>

typedef uint32_t u32;

// ---------------------------------------------------------------------------
// Triaffine, tensor-core fp16 mma (fp32 accum), 3 launches total:
//  prep_all: fp32->fp16 casts of l1/l2/W1/W2 + W3 transpose  (one kernel)
//  K1: X{1,2} = l1(fp16) @ W{1,2}(fp16) + bias  -> g_X fp16  (BK=32, 4-buf)
//  K23 (fused, per (m, 128-j tile)):
//    s1: A_r = l2 @ X2 + bias, *h2  -> smem P (single fp16)
//    s2: T   = P @ W3T (1-term), *h1 -> smem fp32 (overwrites P)
//    s3: A_l = l2 @ X1 + bias;  out[j] = sum_c A_l[j,c] * T[j,c]
// v8 = R14 GEMMs (best known) + merged prep (R15's verified-good half).
// ---------------------------------------------------------------------------

#define WSZ 16908544ull              // 257*65792
#define XSZ (2048ull*65792)

__device__ __half g_L1[2048ull*256], g_L2[2048ull*256];
__device__ __half g_W[2ull*WSZ];                   // W1 | W2 (fp16)
__device__ __half g_X[2ull*XSZ];                   // X1 | X2 (fp16)
__device__ __half g_W3T[256*256];                  // W3T[d][c] (fp16)

// ---- K1 smem (256 threads, 2 CTA/SM): [A 8192 | B 8192] x 4, BK=32 ----
#define BUF12   16384
#define SMEM12  65536

// ---- K23 smem (512 threads, 1 CTA/SM) ----
#define FBUF    24576                // [A 8192 | B 16384] x 3
#define FSM_P   73728                // P fp16 64KB; T fp32 (133120B) overlaps
#define FSM_H   206848               // h1 1KB | h2 1KB
#define FSM_RED 208896               // 4 x 128 floats
#define FSMEM   210944

// ---------------- PTX helpers ----------------
__device__ __forceinline__ u32 smem_u32(const void* p) {
    u32 a;
    asm("{ .reg .u64 t; cvta.to.shared.u64 t, %1; cvt.u32.u64 %0, t; }" : "=r"(a) : "l"(p));
    return a;
}
__device__ __forceinline__ void cpa16(u32 s, const void* g) {
    asm volatile("cp.async.cg.shared.global [%0], [%1], 16;" :: "r"(s), "l"(g));
}
#define CPA_COMMIT() asm volatile("cp.async.commit_group;" ::: "memory")
#define CPA_WAIT(n)  asm volatile("cp.async.wait_group %0;" :: "n"(n) : "memory")

__device__ __forceinline__ void ldm_x4(u32 addr, u32 r[4]) {
    asm volatile("ldmatrix.sync.aligned.m8n8.x4.shared.b16 {%0,%1,%2,%3}, [%4];"
        : "=r"(r[0]), "=r"(r[1]), "=r"(r[2]), "=r"(r[3]) : "r"(addr));
}
__device__ __forceinline__ void ldm_x4_t(u32 addr, u32 r[4]) {
    asm volatile("ldmatrix.sync.aligned.m8n8.x4.trans.shared.b16 {%0,%1,%2,%3}, [%4];"
        : "=r"(r[0]), "=r"(r[1]), "=r"(r[2]), "=r"(r[3]) : "r"(addr));
}
__device__ __forceinline__ void mma_f16(float c[4], const u32 a[4], u32 b0, u32 b1) {
    asm volatile("mma.sync.aligned.m16n8k16.row.col.f32.f16.f16.f32 "
        "{%0,%1,%2,%3}, {%4,%5,%6,%7}, {%8,%9}, {%0,%1,%2,%3};"
        : "+f"(c[0]), "+f"(c[1]), "+f"(c[2]), "+f"(c[3])
        : "r"(a[0]), "r"(a[1]), "r"(a[2]), "r"(a[3]), "r"(b0), "r"(b1));
}

// XOR swizzles (c = 16B chunk index within row)
__device__ __forceinline__ u32 sw_a(u32 base, int row, int c) {       // 64B rows
    return base + row * 64 + ((c ^ ((row >> 1) & 3)) << 4);
}
__device__ __forceinline__ u32 sw_b(u32 base, int row, int c) {       // 256B rows
    return base + row * 256 + ((c ^ (row & 7)) << 4);
}
__device__ __forceinline__ u32 sw_b512(u32 base, int row, int c) {    // 512B rows
    return base + row * 512 + ((c ^ (row & 7)) << 4);
}

#define ZERO_ACC(acc)                                                         \
    _Pragma("unroll") for (int mi = 0; mi < 2; ++mi)                          \
    _Pragma("unroll") for (int ni = 0; ni < 8; ++ni)                          \
    _Pragma("unroll") for (int q = 0; q < 4; ++q) acc[mi][ni][q] = 0.0f;

// ---------------------------------------------------------------------------
// K1 building blocks (256 threads, B rows 256B, CTA 128x128, BK=32)
// ---------------------------------------------------------------------------
__device__ __forceinline__ void stage_s(u32 base, int tid,
    const __half* __restrict__ a, size_t apitch,
    const __half* __restrict__ b, size_t bpitch, int k0)
{
    const int arow = tid >> 1, ac = tid & 1;
    const __half* g = a + (size_t)arow * apitch + k0 + ac * 16;
    cpa16(sw_a(base, arow, ac * 2), g);
    cpa16(sw_a(base, arow, ac * 2 + 1), g + 8);
    const int brow = tid >> 3, bc = tid & 7;
    g = b + (size_t)(k0 + brow) * bpitch + bc * 16;
    cpa16(sw_b(base + 8192, brow, bc * 2), g);
    cpa16(sw_b(base + 8192, brow, bc * 2 + 1), g + 8);
}
__device__ __forceinline__ void compute_s(float acc[2][8][4],
        u32 base, int warpM, int warpN, int lane)
{
    const int lr = lane & 15, lh = lane >> 4;
#pragma unroll
    for (int kk = 0; kk < 2; ++kk) {
        u32 af[2][4];
#pragma unroll
        for (int mi = 0; mi < 2; ++mi)
            ldm_x4(sw_a(base, warpM * 32 + mi * 16 + lr, kk * 2 + lh), af[mi]);
#pragma unroll
        for (int np = 0; np < 4; ++np) {
            u32 bf[4];
            ldm_x4_t(sw_b(base + 8192, kk * 16 + lr, warpN * 8 + np * 2 + lh), bf);
#pragma unroll
            for (int mi = 0; mi < 2; ++mi) {
                mma_f16(acc[mi][np*2],   af[mi], bf[0], bf[1]);
                mma_f16(acc[mi][np*2+1], af[mi], bf[2], bf[3]);
            }
        }
    }
}

// ---------------------------------------------------------------------------
// K23 building blocks (512 threads, B rows 512B, CTA 128x256)
// ---------------------------------------------------------------------------
__device__ __forceinline__ void stage_f(u32 base, int tid,
    const __half* __restrict__ a, const __half* __restrict__ b, int k0)
{
    const int arow = tid >> 2, ac = tid & 3;
    cpa16(sw_a(base, arow, ac), a + (size_t)arow * 256 + k0 + ac * 8);
    const int brow = tid >> 4, bc = (tid & 15) * 2;
    const __half* g = b + (size_t)(k0 + brow) * 256 + bc * 8;
    cpa16(sw_b512(base + 8192, brow, bc), g);
    cpa16(sw_b512(base + 8192, brow, bc + 1), g + 8);
}
__device__ __forceinline__ void stage_fB(u32 base, int tid,
    const __half* __restrict__ b, int k0)
{
    const int brow = tid >> 4, bc = (tid & 15) * 2;
    const __half* g = b + (size_t)(k0 + brow) * 256 + bc * 8;
    cpa16(sw_b512(base, brow, bc), g);
    cpa16(sw_b512(base, brow, bc + 1), g + 8);
}
__device__ __forceinline__ void compute_f(float acc[2][8][4],
        u32 base, int warpM, int warpN, int lane)
{
    const int lr = lane & 15, lh = lane >> 4;
#pragma unroll
    for (int kk = 0; kk < 2; ++kk) {
        u32 af[2][4];
#pragma unroll
        for (int mi = 0; mi < 2; ++mi)
            ldm_x4(sw_a(base, warpM * 32 + mi * 16 + lr, kk * 2 + lh), af[mi]);
#pragma unroll
        for (int np = 0; np < 4; ++np) {
            u32 bf[4];
            ldm_x4_t(sw_b512(base + 8192, kk * 16 + lr, warpN * 8 + np * 2 + lh), bf);
#pragma unroll
            for (int mi = 0; mi < 2; ++mi) {
                mma_f16(acc[mi][np*2],   af[mi], bf[0], bf[1]);
                mma_f16(acc[mi][np*2+1], af[mi], bf[2], bf[3]);
            }
        }
    }
}
__device__ __forceinline__ void compute_fp1(float acc[2][8][4],
        u32 pHi, u32 bBase, int sChunk, int warpM, int warpN, int lane)
{
    const int lr = lane & 15, lh = lane >> 4;
#pragma unroll
    for (int kk = 0; kk < 2; ++kk) {
        u32 af[2][4];
#pragma unroll
        for (int mi = 0; mi < 2; ++mi) {
            int row = warpM * 32 + mi * 16 + lr;
            int c = sChunk + kk * 2 + lh;
            u32 off = row * 512 + (((c ^ (row & 7))) << 4);
            ldm_x4(pHi + off, af[mi]);
        }
#pragma unroll
        for (int np = 0; np < 4; ++np) {
            u32 bf[4];
            ldm_x4_t(sw_b512(bBase, kk * 16 + lr, warpN * 8 + np * 2 + lh), bf);
#pragma unroll
            for (int mi = 0; mi < 2; ++mi) {
                mma_f16(acc[mi][np*2],   af[mi], bf[0], bf[1]);
                mma_f16(acc[mi][np*2+1], af[mi], bf[2], bf[3]);
            }
        }
    }
}

// 3-buffer pipeline, prefetch depth 2, one barrier per BK=32 stage (K23)
#define FLOOP(STG, CMP)                                                       \
    STG(0, 0); CPA_COMMIT();                                                  \
    STG(1, 1); CPA_COMMIT();                                                  \
    for (int s = 0; s < 8; ++s) {                                             \
        if (s == 7) { CPA_WAIT(0); } else { CPA_WAIT(1); }                    \
        __syncthreads();                                                      \
        if (s < 6) { STG((s + 2) % 3, s + 2); CPA_COMMIT(); }                 \
        CMP;                                                                  \
    }

// K1 pipeline: 4 buffers, depth 3 (R14 proven best)
#define MAINLOOP12(STG)                                                       \
    STG(0, 0); CPA_COMMIT();                                                  \
    STG(1, 1); CPA_COMMIT();                                                  \
    STG(2, 2); CPA_COMMIT();                                                  \
    for (int s = 0; s < 8; ++s) {                                             \
        if (s <= 5) { CPA_WAIT(2); } else if (s == 6) { CPA_WAIT(1); }        \
        else { CPA_WAIT(0); }                                                 \
        __syncthreads();                                                      \
        if (s < 5) { STG((s + 3) & 3, s + 3); CPA_COMMIT(); }                 \
        compute_s(acc, sb + (s & 3) * BUF12, warpM, warpN, lane);             \
    }

// ---------------------------------------------------------------------------
// prep_all: one kernel. blocks [0,256) L1, [256,512) L2, [512,8769) W1,
// [8769,17026) W2, [17026,17090) W3 transpose.
// ---------------------------------------------------------------------------
__global__ void k_prep_all(const float* __restrict__ layer1,
                           const float* __restrict__ layer2,
                           const float* __restrict__ W1,
                           const float* __restrict__ W2,
                           const float* __restrict__ W3)
{
    const int bid = blockIdx.x, tid = threadIdx.x;
    if (bid < 17026) {
        const float* src;
        __half* d;
        size_t base, cnt;
        if (bid < 256)       { src = layer1; d = g_L1;      base = (size_t)bid * 2048;               cnt = 524288ull; }
        else if (bid < 512)  { src = layer2; d = g_L2;      base = (size_t)(bid - 256) * 2048;       cnt = 524288ull; }
        else if (bid < 8769) { src = W1;     d = g_W;       base = (size_t)(bid - 512) * 2048;       cnt = WSZ; }
        else                 { src = W2;     d = g_W + WSZ; base = (size_t)(bid - 8769) * 2048;      cnt = WSZ; }
        size_t i = base + (size_t)tid * 8;
        if (i >= cnt) return;
        float4 v0 = *reinterpret_cast<const float4*>(src + i);
        float4 v1 = *reinterpret_cast<const float4*>(src + i + 4);
        float x[8] = {v0.x, v0.y, v0.z, v0.w, v1.x, v1.y, v1.z, v1.w};
        u32 o[4];
#pragma unroll
        for (int j = 0; j < 4; ++j) {
            __half2 h = __floats2half2_rn(x[2*j], x[2*j+1]);
            o[j] = *reinterpret_cast<u32*>(&h);
        }
        *reinterpret_cast<uint4*>(d + i) = make_uint4(o[0], o[1], o[2], o[3]);
    } else {
        __shared__ float t[32][33];
        int tb = bid - 17026;
        int bx = (tb & 7) * 32, by = (tb >> 3) * 32;
        int r0 = tid >> 5, cc = tid & 31;
#pragma unroll
        for (int rr = r0; rr < 32; rr += 8)
            t[rr][cc] = W3[(size_t)(by + rr) * 256 + bx + cc];
        __syncthreads();
#pragma unroll
        for (int rr = r0; rr < 32; rr += 8)
            g_W3T[(size_t)(bx + rr) * 256 + by + cc] = __float2half_rn(t[cc][rr]);
    }
}

// ---------------------------------------------------------------------------
// K1: grid (16 mt, 514 nt, 2 w). D[128 m][128 bc], K=256 over a -> X fp16.
// ---------------------------------------------------------------------------
__global__ void __launch_bounds__(256, 2)
k1_gemm()
{
    extern __shared__ char smem[];
    const int tid = threadIdx.x, lane = tid & 31, wid = tid >> 5;
    const int warpM = wid & 3, warpN = wid >> 2;
    const int mBase = blockIdx.x * 128;
    const size_t n0 = (size_t)blockIdx.y * 128;
    const int w = blockIdx.z;
    const __half* WP = g_W + (size_t)w * WSZ + n0;
    __half* XP       = g_X + (size_t)w * XSZ;
    const __half* AP = g_L1 + (size_t)mBase * 256;
    const u32 sb = smem_u32(smem);

    float acc[2][8][4];
    ZERO_ACC(acc)

#define K1_STAGE(buf, s) stage_s(sb + (buf) * BUF12, tid, AP, 256, WP, 65792, (s) * 32)
    MAINLOOP12(K1_STAGE)
#undef K1_STAGE

    const int gq = lane >> 2, t = lane & 3;
#pragma unroll
    for (int mi = 0; mi < 2; ++mi) {
        int row = mBase + warpM * 32 + mi * 16 + gq;
#pragma unroll
        for (int ni = 0; ni < 8; ++ni) {
            int colL = warpN * 64 + ni * 8 + t * 2;
            __half2 b2 = *reinterpret_cast<const __half2*>(WP + 256ull * 65792 + colL);
            float b0 = __half2float(__low2half(b2));
            float b1 = __half2float(__high2half(b2));
            size_t col = n0 + colL;
            __half2 o0 = __floats2half2_rn(acc[mi][ni][0] + b0, acc[mi][ni][1] + b1);
            __half2 o1 = __floats2half2_rn(acc[mi][ni][2] + b0, acc[mi][ni][3] + b1);
            *reinterpret_cast<__half2*>(XP + (size_t)row * 65792 + col) = o0;
            *reinterpret_cast<__half2*>(XP + (size_t)(row + 8) * 65792 + col) = o1;
        }
    }
}

// ---------------------------------------------------------------------------
// K23 fused: grid (2 jt, 2048 m), 512 threads, CTA tile 128 j x 256 (c|d).
// ---------------------------------------------------------------------------
__global__ void __launch_bounds__(512, 1)
k23_fused(const float* __restrict__ h1, const float* __restrict__ h2,
          float* __restrict__ out)
{
    extern __shared__ char smem[];
    const int tid = threadIdx.x, lane = tid & 31, wid = tid >> 5;
    const int warpM = wid & 3, warpN = wid >> 2;     // 4 x 4 warps
    const int jt = blockIdx.x, m = blockIdx.y;
    const u32 sb = smem_u32(smem);
    const u32 pHi = sb + FSM_P;
    float* Tp  = reinterpret_cast<float*>(smem + FSM_P);     // pitch 260 floats
    float* h1s = reinterpret_cast<float*>(smem + FSM_H);
    float* h2s = reinterpret_cast<float*>(smem + FSM_H + 1024);
    float* red = reinterpret_cast<float*>(smem + FSM_RED);

    const __half* AP  = g_L2 + ((size_t)(m >> 8) * 256 + (size_t)jt * 128) * 256;
    const __half* X1P = g_X + (size_t)m * 65792;
    const __half* X2P = g_X + XSZ + (size_t)m * 65792;

    if (tid < 256) {
        h1s[tid] = h1[(size_t)m * 256 + tid];
        h2s[tid] = h2[(size_t)m * 256 + tid];
    }

    const int gq = lane >> 2, t = lane & 3;
    float acc[2][8][4];

    // ---------------- stage 1: A_r = l2 @ X2 + bias, *h2 -> P fp16 ----------
    ZERO_ACC(acc)
#define S1(buf, s) stage_f(sb + (buf) * FBUF, tid, AP, X2P, (s) * 32)
    FLOOP(S1, compute_f(acc, sb + (s % 3) * FBUF, warpM, warpN, lane))
#undef S1

#pragma unroll
    for (int mi = 0; mi < 2; ++mi) {
        int j0 = warpM * 32 + mi * 16 + gq;
#pragma unroll
        for (int ni = 0; ni < 8; ++ni) {
            int c = warpN * 64 + ni * 8 + t * 2;
            __half2 b2 = *reinterpret_cast<const __half2*>(X2P + 65536 + c);
            float b0 = __half2float(__low2half(b2));
            float b1 = __half2float(__high2half(b2));
            float v00 = (acc[mi][ni][0] + b0) * h2s[c];
            float v01 = (acc[mi][ni][1] + b1) * h2s[c + 1];
            float v10 = (acc[mi][ni][2] + b0) * h2s[c];
            float v11 = (acc[mi][ni][3] + b1) * h2s[c + 1];
            u32 chunk = (u32)(warpN * 8 + ni);
            u32 o0 = j0 * 512 + ((chunk ^ (j0 & 7)) << 4) + t * 4;
            int j1 = j0 + 8;
            u32 o1 = j1 * 512 + ((chunk ^ (j1 & 7)) << 4) + t * 4;
            *reinterpret_cast<__half2*>(smem + FSM_P + o0) =
                __floats2half2_rn(v00, v01);
            *reinterpret_cast<__half2*>(smem + FSM_P + o1) =
                __floats2half2_rn(v10, v11);
        }
    }
    __syncthreads();   // P complete before stage-2 staging/compute

    // ---------------- stage 2: T = P @ W3T (1-term), *h1 -> T ---------------
    ZERO_ACC(acc)
#define S2(buf, s) stage_fB(sb + (buf) * FBUF, tid, g_W3T, (s) * 32)
    FLOOP(S2, compute_fp1(acc, pHi, sb + (s % 3) * FBUF, s * 4, warpM, warpN, lane))
#undef S2

    __syncthreads();   // all P reads done; safe to overwrite with T
#pragma unroll
    for (int mi = 0; mi < 2; ++mi) {
        int j0 = warpM * 32 + mi * 16 + gq;
#pragma unroll
        for (int ni = 0; ni < 8; ++ni) {
            int c = warpN * 64 + ni * 8 + t * 2;
            float s0 = h1s[c], s1 = h1s[c + 1];
            *reinterpret_cast<float2*>(Tp + (size_t)j0 * 260 + c) =
                make_float2(acc[mi][ni][0] * s0, acc[mi][ni][1] * s1);
            *reinterpret_cast<float2*>(Tp + (size_t)(j0 + 8) * 260 + c) =
                make_float2(acc[mi][ni][2] * s0, acc[mi][ni][3] * s1);
        }
    }
    __syncthreads();   // T visible before stage-3 epilogue; bufs free

    // ---------------- stage 3: A_l = l2 @ X1 + bias; dot with T -------------
    ZERO_ACC(acc)
#define S3(buf, s) stage_f(sb + (buf) * FBUF, tid, AP, X1P, (s) * 32)
    FLOOP(S3, compute_f(acc, sb + (s % 3) * FBUF, warpM, warpN, lane))
#undef S3

    float rs[2][2] = {{0.0f, 0.0f}, {0.0f, 0.0f}};
#pragma unroll
    for (int mi = 0; mi < 2; ++mi) {
        int j0 = warpM * 32 + mi * 16 + gq;
#pragma unroll
        for (int ni = 0; ni < 8; ++ni) {
            int c = warpN * 64 + ni * 8 + t * 2;
            __half2 b2 = *reinterpret_cast<const __half2*>(X1P + 65536 + c);
            float b0 = __half2float(__low2half(b2));
            float b1 = __half2float(__high2half(b2));
            float2 t0 = *reinterpret_cast<const float2*>(Tp + (size_t)j0 * 260 + c);
            float2 t1 = *reinterpret_cast<const float2*>(Tp + (size_t)(j0 + 8) * 260 + c);
            rs[mi][0] += (acc[mi][ni][0] + b0) * t0.x + (acc[mi][ni][1] + b1) * t0.y;
            rs[mi][1] += (acc[mi][ni][2] + b0) * t1.x + (acc[mi][ni][3] + b1) * t1.y;
        }
    }

    // reduce over the 4 lanes (t) sharing each row, then across warpN
#pragma unroll
    for (int mi = 0; mi < 2; ++mi)
#pragma unroll
        for (int h = 0; h < 2; ++h) {
            rs[mi][h] += __shfl_xor_sync(0xffffffffu, rs[mi][h], 1);
            rs[mi][h] += __shfl_xor_sync(0xffffffffu, rs[mi][h], 2);
        }
    if (t == 0) {
#pragma unroll
        for (int mi = 0; mi < 2; ++mi) {
            red[warpN * 128 + warpM * 32 + mi * 16 + gq]     = rs[mi][0];
            red[warpN * 128 + warpM * 32 + mi * 16 + 8 + gq] = rs[mi][1];
        }
    }
    __syncthreads();
    if (tid < 128)
        out[(size_t)m * 256 + jt * 128 + tid] =
            red[tid] + red[128 + tid] + red[256 + tid] + red[384 + tid];
}

// ---------------------------------------------------------------------------
extern "C" void kernel_launch(void* const* d_in, const int* in_sizes, int n_in,
                              void* d_out, int out_size)
{
    const float* layer1 = (const float*)d_in[0];
    const float* layer2 = (const float*)d_in[1];
    const float* h1     = (const float*)d_in[2];
    const float* h2     = (const float*)d_in[3];
    const float* W1     = (const float*)d_in[4];
    const float* W2     = (const float*)d_in[5];
    const float* W3     = (const float*)d_in[6];
    float* out = (float*)d_out;

    cudaFuncSetAttribute(k1_gemm,   cudaFuncAttributeMaxDynamicSharedMemorySize, SMEM12);
    cudaFuncSetAttribute(k23_fused, cudaFuncAttributeMaxDynamicSharedMemorySize, FSMEM);

    k_prep_all<<<17090, 256>>>(layer1, layer2, W1, W2, W3);
    k1_gemm<<<dim3(16, 514, 2), 256, SMEM12>>>();
    k23_fused<<<dim3(2, 2048), 512, FSMEM>>>(h1, h2, out);
}

// round 17
// speedup vs baseline: 1.0713x; 1.0258x over previous
#include <cuda_runtime.h>
#include <cuda_fp16.h>
#include <cstdint>

typedef uint32_t u32;

// ---------------------------------------------------------------------------
// Triaffine, tensor-core fp16 mma (fp32 accum), 3 launches total:
//  prep_all: fp32->fp16 casts of l1/l2/W1/W2 + W3 transpose  (one kernel)
//  K1: X{1,2} = l1(fp16) @ W{1,2}(fp16) + bias  -> g_X fp16  (BK=32, 4-buf)
//  K23 (fused, per (m, 128-j tile)):
//    s1: A_r = l2 @ X2 + bias, *h2  -> smem P (single fp16)
//    s2: T   = P @ W3T (1-term), *h1 -> smem fp32 (overwrites P)
//    s3: A_l = l2 @ X1 + bias;  out[j] = sum_c A_l[j,c] * T[j,c]
// v9 = v8 + cross-stage prefetch in K23: next stage's chunk-0/1 cp.async
// issued around the boundary barrier so epilogues hide the staging ramp.
// ---------------------------------------------------------------------------

#define WSZ 16908544ull              // 257*65792
#define XSZ (2048ull*65792)

__device__ __half g_L1[2048ull*256], g_L2[2048ull*256];
__device__ __half g_W[2ull*WSZ];                   // W1 | W2 (fp16)
__device__ __half g_X[2ull*XSZ];                   // X1 | X2 (fp16)
__device__ __half g_W3T[256*256];                  // W3T[d][c] (fp16)

// ---- K1 smem (256 threads, 2 CTA/SM): [A 8192 | B 8192] x 4, BK=32 ----
#define BUF12   16384
#define SMEM12  65536

// ---- K23 smem (512 threads, 1 CTA/SM) ----
#define FBUF    24576                // [A 8192 | B 16384] x 3
#define FSM_P   73728                // P fp16 64KB; T fp32 (133120B) overlaps
#define FSM_H   206848               // h1 1KB | h2 1KB
#define FSM_RED 208896               // 4 x 128 floats
#define FSMEM   210944

// ---------------- PTX helpers ----------------
__device__ __forceinline__ u32 smem_u32(const void* p) {
    u32 a;
    asm("{ .reg .u64 t; cvta.to.shared.u64 t, %1; cvt.u32.u64 %0, t; }" : "=r"(a) : "l"(p));
    return a;
}
__device__ __forceinline__ void cpa16(u32 s, const void* g) {
    asm volatile("cp.async.cg.shared.global [%0], [%1], 16;" :: "r"(s), "l"(g));
}
#define CPA_COMMIT() asm volatile("cp.async.commit_group;" ::: "memory")
#define CPA_WAIT(n)  asm volatile("cp.async.wait_group %0;" :: "n"(n) : "memory")

__device__ __forceinline__ void ldm_x4(u32 addr, u32 r[4]) {
    asm volatile("ldmatrix.sync.aligned.m8n8.x4.shared.b16 {%0,%1,%2,%3}, [%4];"
        : "=r"(r[0]), "=r"(r[1]), "=r"(r[2]), "=r"(r[3]) : "r"(addr));
}
__device__ __forceinline__ void ldm_x4_t(u32 addr, u32 r[4]) {
    asm volatile("ldmatrix.sync.aligned.m8n8.x4.trans.shared.b16 {%0,%1,%2,%3}, [%4];"
        : "=r"(r[0]), "=r"(r[1]), "=r"(r[2]), "=r"(r[3]) : "r"(addr));
}
__device__ __forceinline__ void mma_f16(float c[4], const u32 a[4], u32 b0, u32 b1) {
    asm volatile("mma.sync.aligned.m16n8k16.row.col.f32.f16.f16.f32 "
        "{%0,%1,%2,%3}, {%4,%5,%6,%7}, {%8,%9}, {%0,%1,%2,%3};"
        : "+f"(c[0]), "+f"(c[1]), "+f"(c[2]), "+f"(c[3])
        : "r"(a[0]), "r"(a[1]), "r"(a[2]), "r"(a[3]), "r"(b0), "r"(b1));
}

// XOR swizzles (c = 16B chunk index within row)
__device__ __forceinline__ u32 sw_a(u32 base, int row, int c) {       // 64B rows
    return base + row * 64 + ((c ^ ((row >> 1) & 3)) << 4);
}
__device__ __forceinline__ u32 sw_b(u32 base, int row, int c) {       // 256B rows
    return base + row * 256 + ((c ^ (row & 7)) << 4);
}
__device__ __forceinline__ u32 sw_b512(u32 base, int row, int c) {    // 512B rows
    return base + row * 512 + ((c ^ (row & 7)) << 4);
}

#define ZERO_ACC(acc)                                                         \
    _Pragma("unroll") for (int mi = 0; mi < 2; ++mi)                          \
    _Pragma("unroll") for (int ni = 0; ni < 8; ++ni)                          \
    _Pragma("unroll") for (int q = 0; q < 4; ++q) acc[mi][ni][q] = 0.0f;

// ---------------------------------------------------------------------------
// K1 building blocks (256 threads, B rows 256B, CTA 128x128, BK=32)
// ---------------------------------------------------------------------------
__device__ __forceinline__ void stage_s(u32 base, int tid,
    const __half* __restrict__ a, size_t apitch,
    const __half* __restrict__ b, size_t bpitch, int k0)
{
    const int arow = tid >> 1, ac = tid & 1;
    const __half* g = a + (size_t)arow * apitch + k0 + ac * 16;
    cpa16(sw_a(base, arow, ac * 2), g);
    cpa16(sw_a(base, arow, ac * 2 + 1), g + 8);
    const int brow = tid >> 3, bc = tid & 7;
    g = b + (size_t)(k0 + brow) * bpitch + bc * 16;
    cpa16(sw_b(base + 8192, brow, bc * 2), g);
    cpa16(sw_b(base + 8192, brow, bc * 2 + 1), g + 8);
}
__device__ __forceinline__ void compute_s(float acc[2][8][4],
        u32 base, int warpM, int warpN, int lane)
{
    const int lr = lane & 15, lh = lane >> 4;
#pragma unroll
    for (int kk = 0; kk < 2; ++kk) {
        u32 af[2][4];
#pragma unroll
        for (int mi = 0; mi < 2; ++mi)
            ldm_x4(sw_a(base, warpM * 32 + mi * 16 + lr, kk * 2 + lh), af[mi]);
#pragma unroll
        for (int np = 0; np < 4; ++np) {
            u32 bf[4];
            ldm_x4_t(sw_b(base + 8192, kk * 16 + lr, warpN * 8 + np * 2 + lh), bf);
#pragma unroll
            for (int mi = 0; mi < 2; ++mi) {
                mma_f16(acc[mi][np*2],   af[mi], bf[0], bf[1]);
                mma_f16(acc[mi][np*2+1], af[mi], bf[2], bf[3]);
            }
        }
    }
}

// ---------------------------------------------------------------------------
// K23 building blocks (512 threads, B rows 512B, CTA 128x256)
// ---------------------------------------------------------------------------
__device__ __forceinline__ void stage_f(u32 base, int tid,
    const __half* __restrict__ a, const __half* __restrict__ b, int k0)
{
    const int arow = tid >> 2, ac = tid & 3;
    cpa16(sw_a(base, arow, ac), a + (size_t)arow * 256 + k0 + ac * 8);
    const int brow = tid >> 4, bc = (tid & 15) * 2;
    const __half* g = b + (size_t)(k0 + brow) * 256 + bc * 8;
    cpa16(sw_b512(base + 8192, brow, bc), g);
    cpa16(sw_b512(base + 8192, brow, bc + 1), g + 8);
}
__device__ __forceinline__ void stage_fB(u32 base, int tid,
    const __half* __restrict__ b, int k0)
{
    const int brow = tid >> 4, bc = (tid & 15) * 2;
    const __half* g = b + (size_t)(k0 + brow) * 256 + bc * 8;
    cpa16(sw_b512(base, brow, bc), g);
    cpa16(sw_b512(base, brow, bc + 1), g + 8);
}
__device__ __forceinline__ void compute_f(float acc[2][8][4],
        u32 base, int warpM, int warpN, int lane)
{
    const int lr = lane & 15, lh = lane >> 4;
#pragma unroll
    for (int kk = 0; kk < 2; ++kk) {
        u32 af[2][4];
#pragma unroll
        for (int mi = 0; mi < 2; ++mi)
            ldm_x4(sw_a(base, warpM * 32 + mi * 16 + lr, kk * 2 + lh), af[mi]);
#pragma unroll
        for (int np = 0; np < 4; ++np) {
            u32 bf[4];
            ldm_x4_t(sw_b512(base + 8192, kk * 16 + lr, warpN * 8 + np * 2 + lh), bf);
#pragma unroll
            for (int mi = 0; mi < 2; ++mi) {
                mma_f16(acc[mi][np*2],   af[mi], bf[0], bf[1]);
                mma_f16(acc[mi][np*2+1], af[mi], bf[2], bf[3]);
            }
        }
    }
}
__device__ __forceinline__ void compute_fp1(float acc[2][8][4],
        u32 pHi, u32 bBase, int sChunk, int warpM, int warpN, int lane)
{
    const int lr = lane & 15, lh = lane >> 4;
#pragma unroll
    for (int kk = 0; kk < 2; ++kk) {
        u32 af[2][4];
#pragma unroll
        for (int mi = 0; mi < 2; ++mi) {
            int row = warpM * 32 + mi * 16 + lr;
            int c = sChunk + kk * 2 + lh;
            u32 off = row * 512 + (((c ^ (row & 7))) << 4);
            ldm_x4(pHi + off, af[mi]);
        }
#pragma unroll
        for (int np = 0; np < 4; ++np) {
            u32 bf[4];
            ldm_x4_t(sw_b512(bBase, kk * 16 + lr, warpN * 8 + np * 2 + lh), bf);
#pragma unroll
            for (int mi = 0; mi < 2; ++mi) {
                mma_f16(acc[mi][np*2],   af[mi], bf[0], bf[1]);
                mma_f16(acc[mi][np*2+1], af[mi], bf[2], bf[3]);
            }
        }
    }
}

// Pipeline body WITHOUT prologue stages (they are issued at the previous
// stage boundary to overlap epilogues). Expects chunks 0,1 already committed
// as two groups.
#define FLOOP_BODY(STG, CMP)                                                  \
    for (int s = 0; s < 8; ++s) {                                             \
        if (s == 7) { CPA_WAIT(0); } else { CPA_WAIT(1); }                    \
        __syncthreads();                                                      \
        if (s < 6) { STG((s + 2) % 3, s + 2); CPA_COMMIT(); }                 \
        CMP;                                                                  \
    }

// K1 pipeline: 4 buffers, depth 3 (R14 proven best)
#define MAINLOOP12(STG)                                                       \
    STG(0, 0); CPA_COMMIT();                                                  \
    STG(1, 1); CPA_COMMIT();                                                  \
    STG(2, 2); CPA_COMMIT();                                                  \
    for (int s = 0; s < 8; ++s) {                                             \
        if (s <= 5) { CPA_WAIT(2); } else if (s == 6) { CPA_WAIT(1); }        \
        else { CPA_WAIT(0); }                                                 \
        __syncthreads();                                                      \
        if (s < 5) { STG((s + 3) & 3, s + 3); CPA_COMMIT(); }                 \
        compute_s(acc, sb + (s & 3) * BUF12, warpM, warpN, lane);             \
    }

// ---------------------------------------------------------------------------
// prep_all: one kernel. blocks [0,256) L1, [256,512) L2, [512,8769) W1,
// [8769,17026) W2, [17026,17090) W3 transpose.
// ---------------------------------------------------------------------------
__global__ void k_prep_all(const float* __restrict__ layer1,
                           const float* __restrict__ layer2,
                           const float* __restrict__ W1,
                           const float* __restrict__ W2,
                           const float* __restrict__ W3)
{
    const int bid = blockIdx.x, tid = threadIdx.x;
    if (bid < 17026) {
        const float* src;
        __half* d;
        size_t base, cnt;
        if (bid < 256)       { src = layer1; d = g_L1;      base = (size_t)bid * 2048;               cnt = 524288ull; }
        else if (bid < 512)  { src = layer2; d = g_L2;      base = (size_t)(bid - 256) * 2048;       cnt = 524288ull; }
        else if (bid < 8769) { src = W1;     d = g_W;       base = (size_t)(bid - 512) * 2048;       cnt = WSZ; }
        else                 { src = W2;     d = g_W + WSZ; base = (size_t)(bid - 8769) * 2048;      cnt = WSZ; }
        size_t i = base + (size_t)tid * 8;
        if (i >= cnt) return;
        float4 v0 = *reinterpret_cast<const float4*>(src + i);
        float4 v1 = *reinterpret_cast<const float4*>(src + i + 4);
        float x[8] = {v0.x, v0.y, v0.z, v0.w, v1.x, v1.y, v1.z, v1.w};
        u32 o[4];
#pragma unroll
        for (int j = 0; j < 4; ++j) {
            __half2 h = __floats2half2_rn(x[2*j], x[2*j+1]);
            o[j] = *reinterpret_cast<u32*>(&h);
        }
        *reinterpret_cast<uint4*>(d + i) = make_uint4(o[0], o[1], o[2], o[3]);
    } else {
        __shared__ float t[32][33];
        int tb = bid - 17026;
        int bx = (tb & 7) * 32, by = (tb >> 3) * 32;
        int r0 = tid >> 5, cc = tid & 31;
#pragma unroll
        for (int rr = r0; rr < 32; rr += 8)
            t[rr][cc] = W3[(size_t)(by + rr) * 256 + bx + cc];
        __syncthreads();
#pragma unroll
        for (int rr = r0; rr < 32; rr += 8)
            g_W3T[(size_t)(bx + rr) * 256 + by + cc] = __float2half_rn(t[cc][rr]);
    }
}

// ---------------------------------------------------------------------------
// K1: grid (16 mt, 514 nt, 2 w). D[128 m][128 bc], K=256 over a -> X fp16.
// ---------------------------------------------------------------------------
__global__ void __launch_bounds__(256, 2)
k1_gemm()
{
    extern __shared__ char smem[];
    const int tid = threadIdx.x, lane = tid & 31, wid = tid >> 5;
    const int warpM = wid & 3, warpN = wid >> 2;
    const int mBase = blockIdx.x * 128;
    const size_t n0 = (size_t)blockIdx.y * 128;
    const int w = blockIdx.z;
    const __half* WP = g_W + (size_t)w * WSZ + n0;
    __half* XP       = g_X + (size_t)w * XSZ;
    const __half* AP = g_L1 + (size_t)mBase * 256;
    const u32 sb = smem_u32(smem);

    float acc[2][8][4];
    ZERO_ACC(acc)

#define K1_STAGE(buf, s) stage_s(sb + (buf) * BUF12, tid, AP, 256, WP, 65792, (s) * 32)
    MAINLOOP12(K1_STAGE)
#undef K1_STAGE

    const int gq = lane >> 2, t = lane & 3;
#pragma unroll
    for (int mi = 0; mi < 2; ++mi) {
        int row = mBase + warpM * 32 + mi * 16 + gq;
#pragma unroll
        for (int ni = 0; ni < 8; ++ni) {
            int colL = warpN * 64 + ni * 8 + t * 2;
            __half2 b2 = *reinterpret_cast<const __half2*>(WP + 256ull * 65792 + colL);
            float b0 = __half2float(__low2half(b2));
            float b1 = __half2float(__high2half(b2));
            size_t col = n0 + colL;
            __half2 o0 = __floats2half2_rn(acc[mi][ni][0] + b0, acc[mi][ni][1] + b1);
            __half2 o1 = __floats2half2_rn(acc[mi][ni][2] + b0, acc[mi][ni][3] + b1);
            *reinterpret_cast<__half2*>(XP + (size_t)row * 65792 + col) = o0;
            *reinterpret_cast<__half2*>(XP + (size_t)(row + 8) * 65792 + col) = o1;
        }
    }
}

// ---------------------------------------------------------------------------
// K23 fused: grid (2 jt, 2048 m), 512 threads, CTA tile 128 j x 256 (c|d).
// Cross-stage prefetch: at each boundary, next stage's chunk 0 is staged
// right after the mainloop (buf0 dead: all warps passed the s=7 barrier),
// chunk 1 right after the boundary __syncthreads (buf1 dead then).
// ---------------------------------------------------------------------------
__global__ void __launch_bounds__(512, 1)
k23_fused(const float* __restrict__ h1, const float* __restrict__ h2,
          float* __restrict__ out)
{
    extern __shared__ char smem[];
    const int tid = threadIdx.x, lane = tid & 31, wid = tid >> 5;
    const int warpM = wid & 3, warpN = wid >> 2;     // 4 x 4 warps
    const int jt = blockIdx.x, m = blockIdx.y;
    const u32 sb = smem_u32(smem);
    const u32 pHi = sb + FSM_P;
    float* Tp  = reinterpret_cast<float*>(smem + FSM_P);     // pitch 260 floats
    float* h1s = reinterpret_cast<float*>(smem + FSM_H);
    float* h2s = reinterpret_cast<float*>(smem + FSM_H + 1024);
    float* red = reinterpret_cast<float*>(smem + FSM_RED);

    const __half* AP  = g_L2 + ((size_t)(m >> 8) * 256 + (size_t)jt * 128) * 256;
    const __half* X1P = g_X + (size_t)m * 65792;
    const __half* X2P = g_X + XSZ + (size_t)m * 65792;

    if (tid < 256) {
        h1s[tid] = h1[(size_t)m * 256 + tid];
        h2s[tid] = h2[(size_t)m * 256 + tid];
    }

    const int gq = lane >> 2, t = lane & 3;
    float acc[2][8][4];

#define S1(buf, s) stage_f(sb + (buf) * FBUF, tid, AP, X2P, (s) * 32)
#define S2(buf, s) stage_fB(sb + (buf) * FBUF, tid, g_W3T, (s) * 32)
#define S3(buf, s) stage_f(sb + (buf) * FBUF, tid, AP, X1P, (s) * 32)

    // ---------------- stage 1: A_r = l2 @ X2 + bias, *h2 -> P fp16 ----------
    ZERO_ACC(acc)
    S1(0, 0); CPA_COMMIT();
    S1(1, 1); CPA_COMMIT();
    FLOOP_BODY(S1, compute_f(acc, sb + (s % 3) * FBUF, warpM, warpN, lane))

    // prefetch s2 chunk 0 (buf0 dead: all warps synced at s=7 before compute)
    S2(0, 0); CPA_COMMIT();

#pragma unroll
    for (int mi = 0; mi < 2; ++mi) {
        int j0 = warpM * 32 + mi * 16 + gq;
#pragma unroll
        for (int ni = 0; ni < 8; ++ni) {
            int c = warpN * 64 + ni * 8 + t * 2;
            __half2 b2 = *reinterpret_cast<const __half2*>(X2P + 65536 + c);
            float b0 = __half2float(__low2half(b2));
            float b1 = __half2float(__high2half(b2));
            float v00 = (acc[mi][ni][0] + b0) * h2s[c];
            float v01 = (acc[mi][ni][1] + b1) * h2s[c + 1];
            float v10 = (acc[mi][ni][2] + b0) * h2s[c];
            float v11 = (acc[mi][ni][3] + b1) * h2s[c + 1];
            u32 chunk = (u32)(warpN * 8 + ni);
            u32 o0 = j0 * 512 + ((chunk ^ (j0 & 7)) << 4) + t * 4;
            int j1 = j0 + 8;
            u32 o1 = j1 * 512 + ((chunk ^ (j1 & 7)) << 4) + t * 4;
            *reinterpret_cast<__half2*>(smem + FSM_P + o0) =
                __floats2half2_rn(v00, v01);
            *reinterpret_cast<__half2*>(smem + FSM_P + o1) =
                __floats2half2_rn(v10, v11);
        }
    }
    __syncthreads();   // P complete; buf1 dead (everyone past s1 chunk 7)

    // ---------------- stage 2: T = P @ W3T (1-term), *h1 -> T ---------------
    S2(1, 1); CPA_COMMIT();   // prefetch s2 chunk 1
    ZERO_ACC(acc)
    FLOOP_BODY(S2, compute_fp1(acc, pHi, sb + (s % 3) * FBUF, s * 4, warpM, warpN, lane))

    // prefetch s3 chunk 0 (buf0 dead)
    S3(0, 0); CPA_COMMIT();

    __syncthreads();   // all P reads done; safe to overwrite with T; buf1 dead
    S3(1, 1); CPA_COMMIT();   // prefetch s3 chunk 1
#pragma unroll
    for (int mi = 0; mi < 2; ++mi) {
        int j0 = warpM * 32 + mi * 16 + gq;
#pragma unroll
        for (int ni = 0; ni < 8; ++ni) {
            int c = warpN * 64 + ni * 8 + t * 2;
            float s0 = h1s[c], s1 = h1s[c + 1];
            *reinterpret_cast<float2*>(Tp + (size_t)j0 * 260 + c) =
                make_float2(acc[mi][ni][0] * s0, acc[mi][ni][1] * s1);
            *reinterpret_cast<float2*>(Tp + (size_t)(j0 + 8) * 260 + c) =
                make_float2(acc[mi][ni][2] * s0, acc[mi][ni][3] * s1);
        }
    }
    __syncthreads();   // T visible before stage-3 epilogue reads

    // ---------------- stage 3: A_l = l2 @ X1 + bias; dot with T -------------
    ZERO_ACC(acc)
    FLOOP_BODY(S3, compute_f(acc, sb + (s % 3) * FBUF, warpM, warpN, lane))

#undef S1
#undef S2
#undef S3

    float rs[2][2] = {{0.0f, 0.0f}, {0.0f, 0.0f}};
#pragma unroll
    for (int mi = 0; mi < 2; ++mi) {
        int j0 = warpM * 32 + mi * 16 + gq;
#pragma unroll
        for (int ni = 0; ni < 8; ++ni) {
            int c = warpN * 64 + ni * 8 + t * 2;
            __half2 b2 = *reinterpret_cast<const __half2*>(X1P + 65536 + c);
            float b0 = __half2float(__low2half(b2));
            float b1 = __half2float(__high2half(b2));
            float2 t0 = *reinterpret_cast<const float2*>(Tp + (size_t)j0 * 260 + c);
            float2 t1 = *reinterpret_cast<const float2*>(Tp + (size_t)(j0 + 8) * 260 + c);
            rs[mi][0] += (acc[mi][ni][0] + b0) * t0.x + (acc[mi][ni][1] + b1) * t0.y;
            rs[mi][1] += (acc[mi][ni][2] + b0) * t1.x + (acc[mi][ni][3] + b1) * t1.y;
        }
    }

    // reduce over the 4 lanes (t) sharing each row, then across warpN
#pragma unroll
    for (int mi = 0; mi < 2; ++mi)
#pragma unroll
        for (int h = 0; h < 2; ++h) {
            rs[mi][h] += __shfl_xor_sync(0xffffffffu, rs[mi][h], 1);
            rs[mi][h] += __shfl_xor_sync(0xffffffffu, rs[mi][h], 2);
        }
    if (t == 0) {
#pragma unroll
        for (int mi = 0; mi < 2; ++mi) {
            red[warpN * 128 + warpM * 32 + mi * 16 + gq]     = rs[mi][0];
            red[warpN * 128 + warpM * 32 + mi * 16 + 8 + gq] = rs[mi][1];
        }
    }
    __syncthreads();
    if (tid < 128)
        out[(size_t)m * 256 + jt * 128 + tid] =
            red[tid] + red[128 + tid] + red[256 + tid] + red[384 + tid];
}

// ---------------------------------------------------------------------------
extern "C" void kernel_launch(void* const* d_in, const int* in_sizes, int n_in,
                              void* d_out, int out_size)
{
    const float* layer1 = (const float*)d_in[0];
    const float* layer2 = (const float*)d_in[1];
    const float* h1     = (const float*)d_in[2];
    const float* h2     = (const float*)d_in[3];
    const float* W1     = (const float*)d_in[4];
    const float* W2     = (const float*)d_in[5];
    const float* W3     = (const float*)d_in[6];
    float* out = (float*)d_out;

    cudaFuncSetAttribute(k1_gemm,   cudaFuncAttributeMaxDynamicSharedMemorySize, SMEM12);
    cudaFuncSetAttribute(k23_fused, cudaFuncAttributeMaxDynamicSharedMemorySize, FSMEM);

    k_prep_all<<<17090, 256>>>(layer1, layer2, W1, W2, W3);
    k1_gemm<<<dim3(16, 514, 2), 256, SMEM12>>>();
    k23_fused<<<dim3(2, 2048), 512, FSMEM>>>(h1, h2, out);
}